// round 4
// baseline (speedup 1.0000x reference)
#include <cuda_runtime.h>

// QuantumImagePreprocessor: Heisenberg-picture closed form, 4 patches/thread.
// x: (32,224,224,1) f32, weights: (2,4,3) f32 -> out: (32,112,112,4) f32.
// Thread handles 2 ow-adjacent patches x 2 batch-halves -> float4 loads, amortized coeffs.

#define NB   32
#define IH   224
#define IW   224
#define OH   112
#define OW   112
#define NPATCH (NB * OH * OW)        // 401408
#define HALF   (NPATCH / 2)          // 200704 (float4 index offset for batch+16)
#define BOFF   (16 * IH * IW)        // element offset: batch + 16
#define QW     (OW / 2)              // 56 ow-pairs per row
#define NTHREADS_TOTAL (16 * OH * QW)   // 100352 = 784 * 128

#define THREADS 128
#define PI_F 3.14159265358979323846f

__global__ __launch_bounds__(THREADS)
void qip_kernel(const float* __restrict__ x,
                const float* __restrict__ weights,
                float* __restrict__ out)
{
    __shared__ float4 sS1[4][3];
    __shared__ float4 sC[8];

    int t = threadIdx.x;
    if (t < 4) {
        const float* ww = weights + t * 3;
        float sf, cf, st, ct, so, co;
        __sincosf(ww[0], &sf, &cf);
        __sincosf(ww[1], &st, &ct);
        __sincosf(ww[2], &so, &co);
        float M00 = ct * cf, M01 = -ct * sf, M02 = st;
        float M10 = sf,      M11 = cf;
        float M20 = -st * cf, M21 = st * sf, M22 = ct;
        // rows of S = Sz(om)*M, column 1 negated (absorbs n1 = -sin)
        sS1[t][0] = make_float4(co * M00 - so * M10, -(co * M01 - so * M11), co * M02, 0.f);
        sS1[t][1] = make_float4(so * M00 + co * M10, -(so * M01 + co * M11), so * M02, 0.f);
        sS1[t][2] = make_float4(M20, -M21, M22, 0.f);
    } else if (t == 4 || t == 5) {
        int wA = t - 4;
        int wB = wA + 2;
        const float* wa = weights + 12 + wA * 3;
        const float* wb = weights + 12 + wB * 3;
        float sfa, cfa, sta, cta, sfb, cfb, stb, ctb;
        __sincosf(wa[0], &sfa, &cfa);
        __sincosf(wa[1], &sta, &cta);
        __sincosf(wb[0], &sfb, &cfb);
        __sincosf(wb[1], &stb, &ctb);
        float ax = -sta * cfa, ay = sta * sfa, az = cta;
        float bx = -stb * cfb, by = stb * sfb, bz = ctb;
        if (t == 4) {
            sC[0] = make_float4(bx, by, bz, 0.f);
            sC[2] = make_float4( ax * bx, -ax * by, -ax * bz, -ay * bx);
            sC[3] = make_float4( ay * by,  ay * bz, -az * bx,  az * by);
            sC[4] = make_float4( az * bz, 0.f, 0.f, 0.f);
        } else {
            sC[1] = make_float4(bx, -by, bz, 0.f);
            sC[5] = make_float4( ax * bx, -ax * by, -ax * bz,  ay * bx);
            sC[6] = make_float4( ay * by,  ay * bz, -az * bx,  az * by);
            sC[7] = make_float4( az * bz, 0.f, 0.f, 0.f);
        }
    }
    __syncthreads();

    // hoist coefficients into registers (loop-invariant)
    float4 q00 = sS1[0][0], q01 = sS1[0][1], q02 = sS1[0][2];
    float4 q10 = sS1[1][0], q11 = sS1[1][1], q12 = sS1[1][2];
    float4 q20 = sS1[2][0], q21 = sS1[2][1], q22 = sS1[2][2];
    float4 q30 = sS1[3][0], q31 = sS1[3][1], q32 = sS1[3][2];
    float4 c0  = sC[0],  c1  = sC[1];
    float4 c2a = sC[2],  c2b = sC[3],  c2c = sC[4];
    float4 c3a = sC[5],  c3b = sC[6],  c3c = sC[7];

    int g = blockIdx.x * THREADS + t;       // 0 .. 100351
    int q   = g % QW;
    int tmp = g / QW;
    int oh  = tmp % OH;
    int b   = tmp / OH;                     // 0..15

    const float* base = x + ((size_t)(b * IH + 2 * oh) * IW + 4 * q);
    // 4 front-batched float4 loads (MLP=4)
    float4 ra0 = *(const float4*)(base);
    float4 ra1 = *(const float4*)(base + IW);
    float4 rb0 = *(const float4*)(base + BOFF);
    float4 rb1 = *(const float4*)(base + BOFF + IW);

    // patch pixel sets: [h][j] -> wires 0..3
    float px[4][4] = {
        { ra0.x, ra0.y, ra1.x, ra1.y },   // h=0, j=0
        { ra0.z, ra0.w, ra1.z, ra1.w },   // h=0, j=1
        { rb0.x, rb0.y, rb1.x, rb1.y },   // h=1, j=0
        { rb0.z, rb0.w, rb1.z, rb1.w },   // h=1, j=1
    };

    float4 res[4];
#pragma unroll
    for (int pp = 0; pp < 4; pp++) {
        // per-wire Bloch after layer-1: m_w = S1_w * (sin a cos a, sin a, cos^2 a)
        float s0, cA, s1, cB, s2, cC, s3, cD;
        __sincosf(px[pp][0] * PI_F, &s0, &cA);
        __sincosf(px[pp][1] * PI_F, &s1, &cB);
        __sincosf(px[pp][2] * PI_F, &s2, &cC);
        __sincosf(px[pp][3] * PI_F, &s3, &cD);

        float n00 = s0 * cA, n02 = cA * cA;
        float n10 = s1 * cB, n12 = cB * cB;
        float n20 = s2 * cC, n22 = cC * cC;
        float n30 = s3 * cD, n32 = cD * cD;

        float m0x = fmaf(q00.x, n00, fmaf(q00.y, s0, q00.z * n02));
        float m0y = fmaf(q01.x, n00, fmaf(q01.y, s0, q01.z * n02));
        float m0z = fmaf(q02.x, n00, fmaf(q02.y, s0, q02.z * n02));
        float m1x = fmaf(q10.x, n10, fmaf(q10.y, s1, q10.z * n12));
        float m1y = fmaf(q11.x, n10, fmaf(q11.y, s1, q11.z * n12));
        float m1z = fmaf(q12.x, n10, fmaf(q12.y, s1, q12.z * n12));
        float m2x = fmaf(q20.x, n20, fmaf(q20.y, s2, q20.z * n22));
        float m2y = fmaf(q21.x, n20, fmaf(q21.y, s2, q21.z * n22));
        float m2z = fmaf(q22.x, n20, fmaf(q22.y, s2, q22.z * n22));
        float m3x = fmaf(q30.x, n30, fmaf(q30.y, s3, q30.z * n32));
        float m3y = fmaf(q31.x, n30, fmaf(q31.y, s3, q31.z * n32));
        float m3z = fmaf(q32.x, n30, fmaf(q32.y, s3, q32.z * n32));

        // shared pair products (wires 0,1)
        float xx01 = m0x * m1x;
        float yy01 = m0y * m1y;
        float zz01 = m0z * m1z;
        float xy01 = m0x * m1y;
        float yx01 = m0y * m1x;
        float yz01 = m0y * m1z;
        float zy01 = m0z * m1y;
        // shared outer products (wires 2,3)
        float axx = m2x * m3x;
        float ayx = m2y * m3x;
        float ayy = m2y * m3y;
        float axy = m2x * m3y;
        float azy = m2z * m3y;
        float azz = m2z * m3z;
        float ayz = m2y * m3z;

        float E0 = fmaf(c0.x, axx,
                   fmaf(c0.y, zz01 * ayx,
                        c0.z * (zz01 * m2z)));

        float E1 = fmaf(c1.x, xx01 * m3x,
                   fmaf(c1.y, yy01 * azy,
                        c1.z * (zz01 * azz)));

        float E2 = c2a.x * (xx01 * axx);
        E2 = fmaf(c2a.y, yy01 * ayx, E2);
        E2 = fmaf(c2a.z, yy01 * m2z, E2);
        E2 = fmaf(c2a.w, xy01 * ayy, E2);
        E2 = fmaf(c2b.x, yx01 * axy, E2);
        E2 = fmaf(c2b.y, yx01 * m3z, E2);
        E2 = fmaf(c2b.z, m1z * ayy, E2);
        E2 = fmaf(c2b.w, m0z * axy, E2);
        E2 = fmaf(c2c.x, m0z * m3z, E2);

        float E3 = c3a.x * (m0x * axx);
        E3 = fmaf(c3a.y, yz01 * ayy, E3);
        E3 = fmaf(c3a.z, zy01 * ayz, E3);
        E3 = fmaf(c3a.w, yz01 * axx, E3);
        E3 = fmaf(c3b.x, m0x * ayy, E3);
        E3 = fmaf(c3b.y, m1x * ayz, E3);
        E3 = fmaf(c3b.z, yy01 * m3x, E3);
        E3 = fmaf(c3b.w, xx01 * azy, E3);
        E3 = fmaf(c3c.x, azz, E3);

        res[pp] = make_float4(E0, E1, E2, E3);
    }

    // out float4 index for (b', oh, ow = 2q + j)
    int Q0 = (b * OH + oh) * QW + q;       // ow-pair slot within batch-half
    float4* o = (float4*)out;
    o[2 * Q0 + 0]        = res[0];
    o[2 * Q0 + 1]        = res[1];
    o[2 * Q0 + HALF + 0] = res[2];
    o[2 * Q0 + HALF + 1] = res[3];
}

extern "C" void kernel_launch(void* const* d_in, const int* in_sizes, int n_in,
                              void* d_out, int out_size) {
    const float* x = (const float*)d_in[0];
    const float* w = (const float*)d_in[1];
    float* out = (float*)d_out;
    qip_kernel<<<NTHREADS_TOTAL / THREADS, THREADS>>>(x, w, out);
}

// round 5
// speedup vs baseline: 1.0449x; 1.0449x over previous
#include <cuda_runtime.h>

// QuantumImagePreprocessor: Heisenberg-picture closed form with f32x2-packed math.
// Each thread computes 2 patches (batch b and b+16) packed into the two lanes
// of fma.rn.f32x2 / mul.rn.f32x2 (sm_100a packed fp32).
// x: (32,224,224,1) f32, weights: (2,4,3) f32 -> out: (32,112,112,4) f32.

#define NB   32
#define IH   224
#define IW   224
#define OH   112
#define OW   112
#define NPATCH (NB * OH * OW)        // 401408
#define HALF   (NPATCH / 2)          // 200704
#define BOFF   (16 * IH * IW)        // element offset: batch + 16

#define THREADS 128
#define PI_F 3.14159265358979323846f

typedef unsigned long long f32x2;

__device__ __forceinline__ f32x2 pk(float lo, float hi) {
    f32x2 r; asm("mov.b64 %0, {%1, %2};" : "=l"(r) : "f"(lo), "f"(hi)); return r;
}
__device__ __forceinline__ void upk(f32x2 v, float& lo, float& hi) {
    asm("mov.b64 {%0, %1}, %2;" : "=f"(lo), "=f"(hi) : "l"(v));
}
__device__ __forceinline__ f32x2 fma2(f32x2 a, f32x2 b, f32x2 c) {
    f32x2 r; asm("fma.rn.f32x2 %0, %1, %2, %3;" : "=l"(r) : "l"(a), "l"(b), "l"(c)); return r;
}
__device__ __forceinline__ f32x2 mul2(f32x2 a, f32x2 b) {
    f32x2 r; asm("mul.rn.f32x2 %0, %1, %2;" : "=l"(r) : "l"(a), "l"(b)); return r;
}

// duplicated-coefficient shared layout:
//  [w*9 + r*3 + c] = Q[w][r][c]  (0..35)
//  36..38 = c0 ; 39..41 = c1 ; 42..50 = c2 ; 51..59 = c3
__global__ __launch_bounds__(THREADS)
void qip_kernel(const float* __restrict__ x,
                const float* __restrict__ weights,
                float* __restrict__ out)
{
    __shared__ float2 sD[60];

    int t = threadIdx.x;
    if (t < 4) {
        const float* ww = weights + t * 3;
        float sf, cf, st, ct, so, co;
        __sincosf(ww[0], &sf, &cf);
        __sincosf(ww[1], &st, &ct);
        __sincosf(ww[2], &so, &co);
        float M00 = ct * cf, M01 = -ct * sf, M02 = st;
        float M10 = sf,      M11 = cf;
        float M20 = -st * cf, M21 = st * sf, M22 = ct;
        float q[9];
        q[0] = co * M00 - so * M10; q[1] = -(co * M01 - so * M11); q[2] = co * M02;
        q[3] = so * M00 + co * M10; q[4] = -(so * M01 + co * M11); q[5] = so * M02;
        q[6] = M20;                 q[7] = -M21;                   q[8] = M22;
#pragma unroll
        for (int i = 0; i < 9; i++) sD[t * 9 + i] = make_float2(q[i], q[i]);
    } else if (t == 4 || t == 5) {
        int wA = t - 4;
        const float* wa = weights + 12 + wA * 3;
        const float* wb = weights + 12 + (wA + 2) * 3;
        float sfa, cfa, sta, cta, sfb, cfb, stb, ctb;
        __sincosf(wa[0], &sfa, &cfa);
        __sincosf(wa[1], &sta, &cta);
        __sincosf(wb[0], &sfb, &cfb);
        __sincosf(wb[1], &stb, &ctb);
        float ax = -sta * cfa, ay = sta * sfa, az = cta;
        float bx = -stb * cfb, by = stb * sfb, bz = ctb;
        float v[12];
        if (t == 4) {
            v[0] = bx; v[1] = by; v[2] = bz;                       // c0 -> 36..38
            v[3] =  ax * bx; v[4] = -ax * by; v[5] = -ax * bz;     // c2 -> 42..50
            v[6] = -ay * bx; v[7] =  ay * by; v[8] =  ay * bz;
            v[9] = -az * bx; v[10] =  az * by; v[11] =  az * bz;
            sD[36] = make_float2(v[0], v[0]);
            sD[37] = make_float2(v[1], v[1]);
            sD[38] = make_float2(v[2], v[2]);
#pragma unroll
            for (int i = 0; i < 9; i++) sD[42 + i] = make_float2(v[3 + i], v[3 + i]);
        } else {
            v[0] = bx; v[1] = -by; v[2] = bz;                      // c1 -> 39..41
            v[3] =  ax * bx; v[4] = -ax * by; v[5] = -ax * bz;     // c3 -> 51..59
            v[6] =  ay * bx; v[7] =  ay * by; v[8] =  ay * bz;
            v[9] = -az * bx; v[10] =  az * by; v[11] =  az * bz;
            sD[39] = make_float2(v[0], v[0]);
            sD[40] = make_float2(v[1], v[1]);
            sD[41] = make_float2(v[2], v[2]);
#pragma unroll
            for (int i = 0; i < 9; i++) sD[51 + i] = make_float2(v[3 + i], v[3 + i]);
        }
    }
    __syncthreads();

    const f32x2* D = (const f32x2*)sD;

    int p0 = blockIdx.x * THREADS + t;   // 0 .. HALF-1

    int ow  = p0 % OW;
    int tmp = p0 / OW;
    int oh  = tmp % OH;
    int b   = tmp / OH;

    const float* base = x + ((size_t)(b * IH + 2 * oh) * IW + 2 * ow);
    float2 r0a = *(const float2*)(base);
    float2 r1a = *(const float2*)(base + IW);
    float2 r0b = *(const float2*)(base + BOFF);
    float2 r1b = *(const float2*)(base + BOFF + IW);

    // angles per wire, patches A/B
    float pa[4] = { r0a.x, r0a.y, r1a.x, r1a.y };
    float pb[4] = { r0b.x, r0b.y, r1b.x, r1b.y };

    // per-wire packed basis t0 = (s*c), t1 = (s), t2 = (c*c); then m[w] = Q_w * basis
    f32x2 m0x, m0y, m0z, m1x, m1y, m1z, m2x, m2y, m2z, m3x, m3y, m3z;
#pragma unroll
    for (int w = 0; w < 4; w++) {
        float sA, cA, sB, cB;
        __sincosf(pa[w] * PI_F, &sA, &cA);
        __sincosf(pb[w] * PI_F, &sB, &cB);
        f32x2 t0 = pk(sA * cA, sB * cB);
        f32x2 t1 = pk(sA, sB);
        f32x2 t2 = pk(cA * cA, cB * cB);
        f32x2 rx = fma2(D[w * 9 + 0], t0, fma2(D[w * 9 + 1], t1, mul2(D[w * 9 + 2], t2)));
        f32x2 ry = fma2(D[w * 9 + 3], t0, fma2(D[w * 9 + 4], t1, mul2(D[w * 9 + 5], t2)));
        f32x2 rz = fma2(D[w * 9 + 6], t0, fma2(D[w * 9 + 7], t1, mul2(D[w * 9 + 8], t2)));
        if (w == 0) { m0x = rx; m0y = ry; m0z = rz; }
        else if (w == 1) { m1x = rx; m1y = ry; m1z = rz; }
        else if (w == 2) { m2x = rx; m2y = ry; m2z = rz; }
        else { m3x = rx; m3y = ry; m3z = rz; }
    }

    // shared pair products (wires 0,1) and outer products (wires 2,3)
    f32x2 xx01 = mul2(m0x, m1x);
    f32x2 yy01 = mul2(m0y, m1y);
    f32x2 zz01 = mul2(m0z, m1z);
    f32x2 xy01 = mul2(m0x, m1y);
    f32x2 yx01 = mul2(m0y, m1x);
    f32x2 yz01 = mul2(m0y, m1z);
    f32x2 zy01 = mul2(m0z, m1y);
    f32x2 axx = mul2(m2x, m3x);
    f32x2 ayx = mul2(m2y, m3x);
    f32x2 ayy = mul2(m2y, m3y);
    f32x2 axy = mul2(m2x, m3y);
    f32x2 azy = mul2(m2z, m3y);
    f32x2 azz = mul2(m2z, m3z);
    f32x2 ayz = mul2(m2y, m3z);

    f32x2 E0 = fma2(D[36], axx,
               fma2(D[37], mul2(zz01, ayx),
                    mul2(D[38], mul2(zz01, m2z))));

    f32x2 E1 = fma2(D[39], mul2(xx01, m3x),
               fma2(D[40], mul2(yy01, azy),
                    mul2(D[41], mul2(zz01, azz))));

    f32x2 E2 =      mul2(D[42], mul2(xx01, axx));
    E2 = fma2(D[43], mul2(yy01, ayx), E2);
    E2 = fma2(D[44], mul2(yy01, m2z), E2);
    E2 = fma2(D[45], mul2(xy01, ayy), E2);
    E2 = fma2(D[46], mul2(yx01, axy), E2);
    E2 = fma2(D[47], mul2(yx01, m3z), E2);
    E2 = fma2(D[48], mul2(m1z, ayy), E2);
    E2 = fma2(D[49], mul2(m0z, axy), E2);
    E2 = fma2(D[50], mul2(m0z, m3z), E2);

    f32x2 E3 =      mul2(D[51], mul2(m0x, axx));
    E3 = fma2(D[52], mul2(yz01, ayy), E3);
    E3 = fma2(D[53], mul2(zy01, ayz), E3);
    E3 = fma2(D[54], mul2(yz01, axx), E3);
    E3 = fma2(D[55], mul2(m0x, ayy), E3);
    E3 = fma2(D[56], mul2(m1x, ayz), E3);
    E3 = fma2(D[57], mul2(yy01, m3x), E3);
    E3 = fma2(D[58], mul2(xx01, azy), E3);
    E3 = fma2(D[59], azz, E3);

    float e0a, e0b, e1a, e1b, e2a, e2b, e3a, e3b;
    upk(E0, e0a, e0b);
    upk(E1, e1a, e1b);
    upk(E2, e2a, e2b);
    upk(E3, e3a, e3b);

    float4* o = (float4*)out;
    o[p0]        = make_float4(e0a, e1a, e2a, e3a);
    o[p0 + HALF] = make_float4(e0b, e1b, e2b, e3b);
}

extern "C" void kernel_launch(void* const* d_in, const int* in_sizes, int n_in,
                              void* d_out, int out_size) {
    const float* x = (const float*)d_in[0];
    const float* w = (const float*)d_in[1];
    float* out = (float*)d_out;
    qip_kernel<<<HALF / THREADS, THREADS>>>(x, w, out);
}

// round 6
// speedup vs baseline: 1.0568x; 1.0114x over previous
#include <cuda_runtime.h>

// QuantumImagePreprocessor: Heisenberg closed form, f32x2-packed, LDS.128 coefficients.
// Each thread: 2 patches (batch b and b+16) in the two lanes of fma.rn.f32x2.
// x: (32,224,224,1) f32, weights: (2,4,3) f32 -> out: (32,112,112,4) f32.

#define NB   32
#define IH   224
#define IW   224
#define OH   112
#define OW   112
#define NPATCH (NB * OH * OW)        // 401408
#define HALF   (NPATCH / 2)          // 200704
#define BOFF   (16 * IH * IW)        // element offset: batch + 16

#define THREADS 128
#define PI_F 3.14159265358979323846f

typedef unsigned long long f32x2;

__device__ __forceinline__ f32x2 pk(float lo, float hi) {
    f32x2 r; asm("mov.b64 %0, {%1, %2};" : "=l"(r) : "f"(lo), "f"(hi)); return r;
}
__device__ __forceinline__ void upk(f32x2 v, float& lo, float& hi) {
    asm("mov.b64 {%0, %1}, %2;" : "=f"(lo), "=f"(hi) : "l"(v));
}
__device__ __forceinline__ f32x2 fma2(f32x2 a, f32x2 b, f32x2 c) {
    f32x2 r; asm("fma.rn.f32x2 %0, %1, %2, %3;" : "=l"(r) : "l"(a), "l"(b), "l"(c)); return r;
}
__device__ __forceinline__ f32x2 mul2(f32x2 a, f32x2 b) {
    f32x2 r; asm("mul.rn.f32x2 %0, %1, %2;" : "=l"(r) : "l"(a), "l"(b)); return r;
}

// shared coefficient layout (float2 entries, value duplicated in both lanes):
//  [w*10 + i]  i<9 : Q[w] row-major (matvec), i=9 pad      -> pairs w*5 .. w*5+4
//  [40..42] c0, [43] pad                                    -> pairs 20,21
//  [44..46] c1, [47] pad                                    -> pairs 22,23
//  [48..56] c2, [57] pad                                    -> pairs 24..28
//  [58..66] c3, [67] pad                                    -> pairs 29..33
__global__ __launch_bounds__(THREADS)
void qip_kernel(const float* __restrict__ x,
                const float* __restrict__ weights,
                float* __restrict__ out)
{
    __shared__ __align__(16) float2 sD[68];

    int t = threadIdx.x;
    if (t < 4) {
        const float* ww = weights + t * 3;
        float sf, cf, st, ct, so, co;
        __sincosf(ww[0], &sf, &cf);
        __sincosf(ww[1], &st, &ct);
        __sincosf(ww[2], &so, &co);
        float M00 = ct * cf, M01 = -ct * sf, M02 = st;
        float M10 = sf,      M11 = cf;
        float M20 = -st * cf, M21 = st * sf, M22 = ct;
        float q[10];
        q[0] = co * M00 - so * M10; q[1] = -(co * M01 - so * M11); q[2] = co * M02;
        q[3] = so * M00 + co * M10; q[4] = -(so * M01 + co * M11); q[5] = so * M02;
        q[6] = M20;                 q[7] = -M21;                   q[8] = M22;
        q[9] = 0.f;
#pragma unroll
        for (int i = 0; i < 10; i++) sD[t * 10 + i] = make_float2(q[i], q[i]);
    } else if (t == 4 || t == 5) {
        int wA = t - 4;
        const float* wa = weights + 12 + wA * 3;
        const float* wb = weights + 12 + (wA + 2) * 3;
        float sfa, cfa, sta, cta, sfb, cfb, stb, ctb;
        __sincosf(wa[0], &sfa, &cfa);
        __sincosf(wa[1], &sta, &cta);
        __sincosf(wb[0], &sfb, &cfb);
        __sincosf(wb[1], &stb, &ctb);
        float ax = -sta * cfa, ay = sta * sfa, az = cta;
        float bx = -stb * cfb, by = stb * sfb, bz = ctb;
        if (t == 4) {
            float c0v[4] = { bx, by, bz, 0.f };
#pragma unroll
            for (int i = 0; i < 4; i++) sD[40 + i] = make_float2(c0v[i], c0v[i]);
            float c2v[10] = { ax * bx, -ax * by, -ax * bz,
                             -ay * bx,  ay * by,  ay * bz,
                             -az * bx,  az * by,  az * bz, 0.f };
#pragma unroll
            for (int i = 0; i < 10; i++) sD[48 + i] = make_float2(c2v[i], c2v[i]);
        } else {
            float c1v[4] = { bx, -by, bz, 0.f };
#pragma unroll
            for (int i = 0; i < 4; i++) sD[44 + i] = make_float2(c1v[i], c1v[i]);
            float c3v[10] = { ax * bx, -ax * by, -ax * bz,
                              ay * bx,  ay * by,  ay * bz,
                             -az * bx,  az * by,  az * bz, 0.f };
#pragma unroll
            for (int i = 0; i < 10; i++) sD[58 + i] = make_float2(c3v[i], c3v[i]);
        }
    }
    __syncthreads();

    const ulonglong2* Dq = (const ulonglong2*)sD;   // pair i = floats (2i, 2i+1)

    int p0 = blockIdx.x * THREADS + t;   // 0 .. HALF-1

    // ow = p0 % 112 ; input element offset = 4*p0 - 2*ow  (derivation: oh*IW folds)
    int ow = p0 % OW;
    const float* base = x + (4 * p0 - 2 * ow);

    float2 r0a = *(const float2*)(base);
    float2 r1a = *(const float2*)(base + IW);
    float2 r0b = *(const float2*)(base + BOFF);
    float2 r1b = *(const float2*)(base + BOFF + IW);

    float pa[4] = { r0a.x, r0a.y, r1a.x, r1a.y };
    float pb[4] = { r0b.x, r0b.y, r1b.x, r1b.y };

    f32x2 m0x, m0y, m0z, m1x, m1y, m1z, m2x, m2y, m2z, m3x, m3y, m3z;
#pragma unroll
    for (int w = 0; w < 4; w++) {
        float sA, cA, sB, cB;
        __sincosf(pa[w] * PI_F, &sA, &cA);
        __sincosf(pb[w] * PI_F, &sB, &cB);
        f32x2 t1 = pk(sA, sB);        // s
        f32x2 tc = pk(cA, cB);        // c
        f32x2 t0 = mul2(t1, tc);      // s*c
        f32x2 t2 = mul2(tc, tc);      // c*c
        ulonglong2 j0 = Dq[w * 5 + 0];   // q0,q1
        ulonglong2 j1 = Dq[w * 5 + 1];   // q2,q3
        ulonglong2 j2 = Dq[w * 5 + 2];   // q4,q5
        ulonglong2 j3 = Dq[w * 5 + 3];   // q6,q7
        ulonglong2 j4 = Dq[w * 5 + 4];   // q8,pad
        f32x2 rx = fma2(j0.x, t0, fma2(j0.y, t1, mul2(j1.x, t2)));
        f32x2 ry = fma2(j1.y, t0, fma2(j2.x, t1, mul2(j2.y, t2)));
        f32x2 rz = fma2(j3.x, t0, fma2(j3.y, t1, mul2(j4.x, t2)));
        if (w == 0) { m0x = rx; m0y = ry; m0z = rz; }
        else if (w == 1) { m1x = rx; m1y = ry; m1z = rz; }
        else if (w == 2) { m2x = rx; m2y = ry; m2z = rz; }
        else { m3x = rx; m3y = ry; m3z = rz; }
    }

    // pair products (wires 0,1) and outer products (wires 2,3)
    f32x2 xx01 = mul2(m0x, m1x);
    f32x2 yy01 = mul2(m0y, m1y);
    f32x2 zz01 = mul2(m0z, m1z);
    f32x2 xy01 = mul2(m0x, m1y);
    f32x2 yx01 = mul2(m0y, m1x);
    f32x2 yz01 = mul2(m0y, m1z);
    f32x2 zy01 = mul2(m0z, m1y);
    f32x2 axx = mul2(m2x, m3x);
    f32x2 ayx = mul2(m2y, m3x);
    f32x2 ayy = mul2(m2y, m3y);
    f32x2 axy = mul2(m2x, m3y);
    f32x2 azy = mul2(m2z, m3y);
    f32x2 azz = mul2(m2z, m3z);
    f32x2 ayz = mul2(m2y, m3z);

    ulonglong2 p20 = Dq[20], p21 = Dq[21];
    f32x2 E0 = fma2(p20.x, axx,
               fma2(p20.y, mul2(zz01, ayx),
                    mul2(p21.x, mul2(zz01, m2z))));

    ulonglong2 p22 = Dq[22], p23 = Dq[23];
    f32x2 E1 = fma2(p22.x, mul2(xx01, m3x),
               fma2(p22.y, mul2(yy01, azy),
                    mul2(p23.x, mul2(zz01, azz))));

    ulonglong2 p24 = Dq[24], p25 = Dq[25], p26 = Dq[26], p27 = Dq[27], p28 = Dq[28];
    f32x2 E2 =      mul2(p24.x, mul2(xx01, axx));
    E2 = fma2(p24.y, mul2(yy01, ayx), E2);
    E2 = fma2(p25.x, mul2(yy01, m2z), E2);
    E2 = fma2(p25.y, mul2(xy01, ayy), E2);
    E2 = fma2(p26.x, mul2(yx01, axy), E2);
    E2 = fma2(p26.y, mul2(yx01, m3z), E2);
    E2 = fma2(p27.x, mul2(m1z, ayy), E2);
    E2 = fma2(p27.y, mul2(m0z, axy), E2);
    E2 = fma2(p28.x, mul2(m0z, m3z), E2);

    ulonglong2 p29 = Dq[29], p30 = Dq[30], p31 = Dq[31], p32 = Dq[32], p33 = Dq[33];
    f32x2 E3 =      mul2(p29.x, mul2(m0x, axx));
    E3 = fma2(p29.y, mul2(yz01, ayy), E3);
    E3 = fma2(p30.x, mul2(zy01, ayz), E3);
    E3 = fma2(p30.y, mul2(yz01, axx), E3);
    E3 = fma2(p31.x, mul2(m0x, ayy), E3);
    E3 = fma2(p31.y, mul2(m1x, ayz), E3);
    E3 = fma2(p32.x, mul2(yy01, m3x), E3);
    E3 = fma2(p32.y, mul2(xx01, azy), E3);
    E3 = fma2(p33.x, azz, E3);

    float e0a, e0b, e1a, e1b, e2a, e2b, e3a, e3b;
    upk(E0, e0a, e0b);
    upk(E1, e1a, e1b);
    upk(E2, e2a, e2b);
    upk(E3, e3a, e3b);

    float4* o = (float4*)out;
    o[p0]        = make_float4(e0a, e1a, e2a, e3a);
    o[p0 + HALF] = make_float4(e0b, e1b, e2b, e3b);
}

extern "C" void kernel_launch(void* const* d_in, const int* in_sizes, int n_in,
                              void* d_out, int out_size) {
    const float* x = (const float*)d_in[0];
    const float* w = (const float*)d_in[1];
    float* out = (float*)d_out;
    qip_kernel<<<HALF / THREADS, THREADS>>>(x, w, out);
}